// round 3
// baseline (speedup 1.0000x reference)
#include <cuda_runtime.h>

#define DFEAT 64
#define MAXN 100000
#define MAXE 1600000
#define SCAN_BLK 1024
#define MAX_PARTIALS 128   // ceil(MAXN/SCAN_BLK)=98 <= 128

// Scratch (device globals — no allocation allowed)
__device__ int   g_cnt[MAXN];        // degree histogram
__device__ int   g_offs[MAXN];       // exclusive prefix (CSR row offsets)
__device__ int   g_cursor[MAXN];     // atomic fill cursor
__device__ int   g_blocksum[MAX_PARTIALS];
__device__ int   g_sorted_src[MAXE]; // src ids grouped by dst
__device__ float g_c[(size_t)MAXN * DFEAT]; // mean-aggregated features

// ---------------------------------------------------------------------------
// K1: zero degree counters
// ---------------------------------------------------------------------------
__global__ void zero_cnt(int n) {
    int i = blockIdx.x * blockDim.x + threadIdx.x;
    if (i < n) g_cnt[i] = 0;
}

// ---------------------------------------------------------------------------
// K2: histogram of dst (degrees)
// ---------------------------------------------------------------------------
__global__ void hist_dst(const int* __restrict__ dst, int E) {
    int e = blockIdx.x * blockDim.x + threadIdx.x;
    if (e < E) atomicAdd(&g_cnt[dst[e]], 1);  // no return use -> RED
}

// ---------------------------------------------------------------------------
// K3a: per-block exclusive scan of g_cnt -> g_offs, block totals -> g_blocksum
// ---------------------------------------------------------------------------
__global__ void scan_blocks(int n) {
    __shared__ int sh[SCAN_BLK];
    int i = blockIdx.x * SCAN_BLK + threadIdx.x;
    int v = (i < n) ? g_cnt[i] : 0;
    sh[threadIdx.x] = v;
    __syncthreads();
    #pragma unroll
    for (int off = 1; off < SCAN_BLK; off <<= 1) {
        int t = (threadIdx.x >= off) ? sh[threadIdx.x - off] : 0;
        __syncthreads();
        sh[threadIdx.x] += t;
        __syncthreads();
    }
    if (i < n) g_offs[i] = sh[threadIdx.x] - v;  // exclusive within block
    if (threadIdx.x == SCAN_BLK - 1) g_blocksum[blockIdx.x] = sh[threadIdx.x];
}

// ---------------------------------------------------------------------------
// K3b: exclusive scan of block totals (single block)
// ---------------------------------------------------------------------------
__global__ void scan_partials(int nb) {
    __shared__ int sh[MAX_PARTIALS];
    int v = (threadIdx.x < nb) ? g_blocksum[threadIdx.x] : 0;
    sh[threadIdx.x] = v;
    __syncthreads();
    #pragma unroll
    for (int off = 1; off < MAX_PARTIALS; off <<= 1) {
        int t = (threadIdx.x >= off) ? sh[threadIdx.x - off] : 0;
        __syncthreads();
        sh[threadIdx.x] += t;
        __syncthreads();
    }
    if (threadIdx.x < nb) g_blocksum[threadIdx.x] = sh[threadIdx.x] - v;
}

// ---------------------------------------------------------------------------
// K3c: add block offsets, init cursors
// ---------------------------------------------------------------------------
__global__ void finalize_offs(int n) {
    int i = blockIdx.x * blockDim.x + threadIdx.x;
    if (i < n) {
        int o = g_offs[i] + g_blocksum[i / SCAN_BLK];
        g_offs[i] = o;
        g_cursor[i] = o;
    }
}

// ---------------------------------------------------------------------------
// K4: scatter src into dst-grouped order (counting sort body)
// ---------------------------------------------------------------------------
__global__ void scatter_edges(const int* __restrict__ src,
                              const int* __restrict__ dst, int E) {
    int e = blockIdx.x * blockDim.x + threadIdx.x;
    if (e < E) {
        int pos = atomicAdd(&g_cursor[dst[e]], 1);
        g_sorted_src[pos] = src[e];
    }
}

// ---------------------------------------------------------------------------
// K5: gather-mean. One warp per node: plain adds, no atomics.
// Lane owns feature columns [2*lane, 2*lane+1] via float2.
// ---------------------------------------------------------------------------
__global__ void gather_mean(const float* __restrict__ h, int n) {
    int w = (blockIdx.x * blockDim.x + threadIdx.x) >> 5;
    int lane = threadIdx.x & 31;
    if (w >= n) return;

    int off = g_offs[w];
    int deg = g_cnt[w];

    float2 acc = make_float2(0.f, 0.f);
    for (int base = 0; base < deg; base += 32) {
        int k = base + lane;
        int s = (k < deg) ? g_sorted_src[off + k] : 0;
        int m = deg - base; if (m > 32) m = 32;
        for (int j = 0; j < m; j++) {
            int sj = __shfl_sync(0xFFFFFFFFu, s, j);
            float2 v = __ldg((const float2*)(h + (size_t)sj * DFEAT) + lane);
            acc.x += v.x;
            acc.y += v.y;
        }
    }
    float inv = 1.0f / fmaxf((float)deg, 1.0f);
    acc.x *= inv; acc.y *= inv;
    ((float2*)(g_c + (size_t)w * DFEAT))[lane] = acc;
}

// ---------------------------------------------------------------------------
// K6: node update. bundle = [h,c] @ W^T + b; L2 normalize; relu; mask; residual.
// One warp processes 8 nodes; W in padded shared (stride 132 -> LDS.128 clean).
// ---------------------------------------------------------------------------
#define WPB 4
#define NPW 8
#define WSTRIDE 132

__global__ void node_update(const float* __restrict__ h,
                            const float* __restrict__ W,
                            const float* __restrict__ b,
                            float* __restrict__ out,
                            int n) {
    extern __shared__ float smem[];
    float* Ws = smem;
    float* bs = Ws + 64 * WSTRIDE;
    float* hc = bs + 64;

    int tid = threadIdx.x;
    for (int i = tid; i < 64 * 128; i += blockDim.x) {
        int r = i >> 7, c = i & 127;
        Ws[r * WSTRIDE + c] = W[i];
    }
    if (tid < 64) bs[tid] = b[tid];
    __syncthreads();

    int lane = tid & 31;
    int warp = tid >> 5;
    float* hcw = hc + warp * (NPW * 128);

    int warpGlobal = blockIdx.x * WPB + warp;
    int numWarps = gridDim.x * WPB;

    const float4* w0p = (const float4*)(Ws + lane * WSTRIDE);
    const float4* w1p = (const float4*)(Ws + lane * WSTRIDE + 64);
    const float4* w2p = (const float4*)(Ws + (lane + 32) * WSTRIDE);
    const float4* w3p = (const float4*)(Ws + (lane + 32) * WSTRIDE + 64);

    for (int base = warpGlobal * NPW; base < n; base += numWarps * NPW) {
        int cnt = n - base; if (cnt > NPW) cnt = NPW;
        int degs[NPW];

        #pragma unroll
        for (int j = 0; j < NPW; j++) {
            int node = base + j;
            if (j < cnt) {
                float2 hv = *(const float2*)(h + (size_t)node * 64 + lane * 2);
                float2 cv = *(const float2*)(g_c + (size_t)node * 64 + lane * 2);
                degs[j] = g_cnt[node];
                ((float2*)(hcw + j * 128))[lane] = hv;
                ((float2*)(hcw + j * 128 + 64))[lane] = cv;
            } else {
                degs[j] = 0;
                ((float2*)(hcw + j * 128))[lane] = make_float2(0.f, 0.f);
                ((float2*)(hcw + j * 128 + 64))[lane] = make_float2(0.f, 0.f);
            }
        }
        __syncwarp();

        float acc0[NPW], acc1[NPW];
        #pragma unroll
        for (int j = 0; j < NPW; j++) { acc0[j] = bs[lane]; acc1[j] = bs[lane + 32]; }

        #pragma unroll
        for (int k4 = 0; k4 < 16; k4++) {
            float4 w0 = w0p[k4];
            float4 w1 = w1p[k4];
            float4 w2 = w2p[k4];
            float4 w3 = w3p[k4];
            #pragma unroll
            for (int j = 0; j < NPW; j++) {
                float4 hk = *(const float4*)(hcw + j * 128 + k4 * 4);
                float4 ck = *(const float4*)(hcw + j * 128 + 64 + k4 * 4);
                acc0[j] += w0.x * hk.x + w0.y * hk.y + w0.z * hk.z + w0.w * hk.w;
                acc0[j] += w1.x * ck.x + w1.y * ck.y + w1.z * ck.z + w1.w * ck.w;
                acc1[j] += w2.x * hk.x + w2.y * hk.y + w2.z * hk.z + w2.w * hk.w;
                acc1[j] += w3.x * ck.x + w3.y * ck.y + w3.z * ck.z + w3.w * ck.w;
            }
        }

        #pragma unroll
        for (int j = 0; j < NPW; j++) {
            float ss = acc0[j] * acc0[j] + acc1[j] * acc1[j];
            #pragma unroll
            for (int o = 16; o > 0; o >>= 1)
                ss += __shfl_xor_sync(0xFFFFFFFFu, ss, o);
            float inv = 1.0f / fmaxf(sqrtf(ss), 1e-12f);
            if (j < cnt) {
                int node = base + j;
                float h0 = hcw[j * 128 + lane];
                float h1 = hcw[j * 128 + lane + 32];
                bool has = degs[j] > 0;
                float u0 = has ? fmaxf(acc0[j] * inv, 0.f) : h0;
                float u1 = has ? fmaxf(acc1[j] * inv, 0.f) : h1;
                out[(size_t)node * 64 + lane] = h0 + u0;
                out[(size_t)node * 64 + lane + 32] = h1 + u1;
            }
        }
        __syncwarp();
    }
}

// ---------------------------------------------------------------------------
extern "C" void kernel_launch(void* const* d_in, const int* in_sizes, int n_in,
                              void* d_out, int out_size) {
    const float* h   = (const float*)d_in[0];
    const float* W   = (const float*)d_in[1];
    const float* b   = (const float*)d_in[2];
    const int*   src = (const int*)d_in[3];
    const int*   dst = (const int*)d_in[4];
    float* out = (float*)d_out;

    int n = in_sizes[0] / DFEAT;
    int E = in_sizes[3];

    int nb = (n + SCAN_BLK - 1) / SCAN_BLK;

    zero_cnt<<<(n + 255) / 256, 256>>>(n);
    hist_dst<<<(E + 255) / 256, 256>>>(dst, E);
    scan_blocks<<<nb, SCAN_BLK>>>(n);
    scan_partials<<<1, MAX_PARTIALS>>>(nb);
    finalize_offs<<<(n + 255) / 256, 256>>>(n);
    scatter_edges<<<(E + 255) / 256, 256>>>(src, dst, E);

    {
        long long threads = (long long)n * 32;
        int blocks = (int)((threads + 255) / 256);
        gather_mean<<<blocks, 256>>>(h, n);
    }

    {
        int smemBytes = (64 * WSTRIDE + 64 + WPB * NPW * 128) * (int)sizeof(float);
        cudaFuncSetAttribute(node_update, cudaFuncAttributeMaxDynamicSharedMemorySize,
                             smemBytes);
        node_update<<<592, WPB * 32, smemBytes>>>(h, W, b, out, n);
    }
}